// round 9
// baseline (speedup 1.0000x reference)
#include <cuda_runtime.h>
#include <cuda_bf16.h>
#include <math.h>
#include <stdint.h>

#define N_ROWS 4096
#define D      256
#define TWO_N  8192
#define BM 128
#define BN 128
#define BK 32
#define NKT (D / BK)              // 8 k-chunks
#define NCOLTILES 64
#define NLOSSBLK (N_ROWS / 8)     // 512 loss blocks
#define NTILES 1552
#define GRID_GEMM 296             // 2 CTAs per SM, persistent

// exp(x/T) = 2^(x * invT * log2(e))
__device__ __constant__ float c_l2T  = 20.609929f;
__device__ __constant__ float c_invT = 14.285714285714286f;

// Scratch (device globals; no allocation anywhere)
__device__ __nv_bfloat16  g_hi[TWO_N * D];       // bf16 normalized
__device__ float          g_partial[N_ROWS * NCOLTILES];
__device__ float          g_blocksum[NLOSSBLK];
__device__ int            g_counter = 0;         // loss last-block counter
__device__ int            g_tileCtr = 0;         // GEMM work-steal counter

// ---------------------------------------------------------------------------
// PTX helpers (sm_80+ baseline only)
// ---------------------------------------------------------------------------
__device__ __forceinline__ uint32_t smem_to_u32(const void* p) {
    uint32_t a;
    asm("{ .reg .u64 t; cvta.to.shared.u64 t, %1; cvt.u32.u64 %0, t; }" : "=r"(a) : "l"(p));
    return a;
}
__device__ __forceinline__ float ex2(float x) {
    float r;
    asm("ex2.approx.ftz.f32 %0, %1;" : "=f"(r) : "f"(x));
    return r;
}
#define CP_ASYNC16(dst, src) \
    asm volatile("cp.async.cg.shared.global [%0], [%1], 16;" :: "r"(dst), "l"(src))
#define CP_COMMIT() asm volatile("cp.async.commit_group;" ::: "memory")
#define CP_WAIT(n)  asm volatile("cp.async.wait_group %0;" :: "n"(n) : "memory")

__device__ __forceinline__ void ldsm4(uint32_t* r, uint32_t addr) {
    asm volatile("ldmatrix.sync.aligned.m8n8.x4.shared.b16 {%0,%1,%2,%3}, [%4];"
        : "=r"(r[0]), "=r"(r[1]), "=r"(r[2]), "=r"(r[3]) : "r"(addr));
}
__device__ __forceinline__ void mma16816(float* c, const uint32_t* a,
                                         uint32_t b0, uint32_t b1) {
    asm volatile("mma.sync.aligned.m16n8k16.row.col.f32.bf16.bf16.f32 "
        "{%0,%1,%2,%3}, {%4,%5,%6,%7}, {%8,%9}, {%0,%1,%2,%3};"
        : "+f"(c[0]), "+f"(c[1]), "+f"(c[2]), "+f"(c[3])
        : "r"(a[0]), "r"(a[1]), "r"(a[2]), "r"(a[3]), "r"(b0), "r"(b1));
}

// Stage: 128 rows x 128B (8x16B chunks). Chunks 0-3 = A, 4-7 = B.
// XOR swizzle: slot = ch ^ (row & 7) -> conflict-free ldmatrix.
__device__ __forceinline__ uint32_t swadr(uint32_t base, int rowByte, int rm, int ch) {
    return base + rowByte + ((ch ^ rm) << 4);
}

#define STAGE_BYTES 16384
#define SCRATCH_OFF (2 * STAGE_BYTES)            // 32768: dedicated epilogue scratch
#define SMEM_TOTAL  (SCRATCH_OFF + 3072)         // 35840 B

// ---------------------------------------------------------------------------
// Kernel 1: L2-normalize rows -> g_hi (bf16). One warp per row.
// ---------------------------------------------------------------------------
__global__ void __launch_bounds__(256) normalize_kernel(const float* __restrict__ z1,
                                                        const float* __restrict__ z2) {
    const int row  = blockIdx.x * 8 + (threadIdx.x >> 5);
    const int lane = threadIdx.x & 31;
    const float* src = (row < N_ROWS) ? (z1 + (size_t)row * D)
                                      : (z2 + (size_t)(row - N_ROWS) * D);
    float4 a = reinterpret_cast<const float4*>(src)[lane];
    float4 b = reinterpret_cast<const float4*>(src)[lane + 32];
    float ss = a.x*a.x + a.y*a.y + a.z*a.z + a.w*a.w
             + b.x*b.x + b.y*b.y + b.z*b.z + b.w*b.w;
    #pragma unroll
    for (int off = 16; off > 0; off >>= 1)
        ss += __shfl_xor_sync(0xffffffffu, ss, off);
    float scale = 1.0f / fmaxf(sqrtf(ss), 1e-12f);

    float v[8] = {a.x*scale, a.y*scale, a.z*scale, a.w*scale,
                  b.x*scale, b.y*scale, b.z*scale, b.w*scale};
    __nv_bfloat162* dh = reinterpret_cast<__nv_bfloat162*>(g_hi + (size_t)row * D);
    dh[lane * 2 + 0]        = __halves2bfloat162(__float2bfloat16(v[0]), __float2bfloat16(v[1]));
    dh[lane * 2 + 1]        = __halves2bfloat162(__float2bfloat16(v[2]), __float2bfloat16(v[3]));
    dh[(lane + 32) * 2 + 0] = __halves2bfloat162(__float2bfloat16(v[4]), __float2bfloat16(v[5]));
    dh[(lane + 32) * 2 + 1] = __halves2bfloat162(__float2bfloat16(v[6]), __float2bfloat16(v[7]));
}

// ---------------------------------------------------------------------------
// Stage loader: A 128x32 (chunks 0-3) + B 128x32 (chunks 4-7) = 1024 16B chunks
// ---------------------------------------------------------------------------
__device__ __forceinline__ void load_stage(uint32_t stageAddr, int kt,
                                           int rowBase, int colBase, int tid) {
    const int kOff = kt * BK;
    #pragma unroll
    for (int i = 0; i < 4; i++) {
        const int v = i * 256 + tid;
        const int row = v >> 3, ch = v & 7;       // ch 0-3: A, 4-7: B
        const int gRow = (ch < 4) ? (rowBase + row) : (colBase + row);
        const void* src = g_hi + (size_t)gRow * D + kOff + (ch & 3) * 8;
        const uint32_t dst = stageAddr + row * 128 + ((ch ^ (row & 7)) << 4);
        CP_ASYNC16(dst, src);
    }
}

// Tile decode: b<1024 -> right half (bx=b>>5, ct=32+(b&31)); else triangular.
__device__ __forceinline__ void decode_tile(int b, int& bx, int& ct, bool& sym) {
    if (b < 1024) {
        bx = b >> 5; ct = 32 + (b & 31); sym = false;
    } else {
        const int t = b - 1024;
        int e = (int)((sqrtf(8.0f * t + 1.0f) - 1.0f) * 0.5f);
        while ((e + 1) * (e + 2) / 2 <= t) e++;
        while (e * (e + 1) / 2 > t) e--;
        bx = e; ct = t - e * (e + 1) / 2; sym = (ct != bx);
    }
}

// ---------------------------------------------------------------------------
// Kernel 2: persistent HMMA fused sim-GEMM + exp + row/col sums.
// R7 pipeline (BK=32, 2-stage, cross-tile prefetch) + dynamic work stealing.
// sh_next: written by tid0 at loop top, read at kt==4 (many syncs later),
// used for next-tile prefetch at kt==7.
// ---------------------------------------------------------------------------
__global__ void __launch_bounds__(256, 2) simsum_mma_kernel() {
    extern __shared__ char smem[];
    const uint32_t smem_u32 = smem_to_u32(smem);
    const int tid = threadIdx.x;

    __shared__ int sh_next;

    const int lane  = tid & 31;
    const int w     = tid >> 5;
    const int warpM = w >> 1;
    const int warpN = w & 1;

    const int aRow  = warpM * 32 + (lane & 7) + ((lane >> 3) & 1) * 8;
    const int aCh   = (lane >> 4) & 1;
    const int aRm   = aRow & 7;
    const int bRow  = warpN * 64 + (lane & 7) + ((lane >> 4) & 1) * 8;
    const int bCh   = (lane >> 3) & 1;
    const int bRm   = bRow & 7;
    const int aRowByte[2] = {aRow * 128, (aRow + 16) * 128};
    const int bRowByte[4] = {bRow * 128, (bRow + 16) * 128,
                             (bRow + 32) * 128, (bRow + 48) * 128};

    float* rowScratch = reinterpret_cast<float*>(smem + SCRATCH_OFF);        // [2][128]
    float* colScratch = reinterpret_cast<float*>(smem + SCRATCH_OFF) + 256;  // [2][4][64]

    // First tile grab
    if (tid == 0) sh_next = atomicAdd(&g_tileCtr, 1);
    __syncthreads();
    int tile = sh_next;
    if (tile >= NTILES) return;

    int bx, colTile; bool sym;
    decode_tile(tile, bx, colTile, sym);
    int rowBase = bx * BM, colBase = colTile * BN;

    int chunk = 0;                 // global chunk parity counter
    load_stage(smem_u32, 0, rowBase, colBase, tid);
    CP_COMMIT();

    #pragma unroll 1
    while (true) {
        // Grab next tile; becomes visible to all threads via chunk syncs.
        if (tid == 0) sh_next = atomicAdd(&g_tileCtr, 1);

        int nTile = 0, nbx = 0, nct = 0; bool nsym = false, hasNext = false;
        int nRowBase = 0, nColBase = 0;

        float acc[2][8][4];
        #pragma unroll
        for (int mt = 0; mt < 2; mt++)
            #pragma unroll
            for (int nt = 0; nt < 8; nt++)
                #pragma unroll
                for (int r = 0; r < 4; r++) acc[mt][nt][r] = 0.0f;

        #pragma unroll 1
        for (int kt = 0; kt < NKT; kt++) {
            const uint32_t stage  = smem_u32 + (uint32_t)(chunk & 1) * STAGE_BYTES;
            const uint32_t nstage = smem_u32 + (uint32_t)((chunk + 1) & 1) * STAGE_BYTES;
            if (kt + 1 < NKT) {
                load_stage(nstage, kt + 1, rowBase, colBase, tid);
                CP_COMMIT(); CP_WAIT(1);
            } else if (hasNext) {
                load_stage(nstage, 0, nRowBase, nColBase, tid);
                CP_COMMIT(); CP_WAIT(1);
            } else {
                CP_WAIT(0);
            }
            __syncthreads();

            if (kt == 4) {         // sh_next published by kt=0..3 syncs
                nTile = sh_next;
                hasNext = (nTile < NTILES);
                if (hasNext) {
                    decode_tile(nTile, nbx, nct, nsym);
                    nRowBase = nbx * BM; nColBase = nct * BN;
                }
            }

            #pragma unroll
            for (int s = 0; s < 2; s++) {
                uint32_t ah[2][4], bh[4][4];
                #pragma unroll
                for (int mt = 0; mt < 2; mt++)
                    ldsm4(ah[mt], swadr(stage, aRowByte[mt], aRm, 2 * s + aCh));
                #pragma unroll
                for (int p = 0; p < 4; p++)
                    ldsm4(bh[p], swadr(stage, bRowByte[p], bRm, 4 + 2 * s + bCh));
                #pragma unroll
                for (int mt = 0; mt < 2; mt++)
                    #pragma unroll
                    for (int nt = 0; nt < 8; nt++)
                        mma16816(acc[mt][nt], ah[mt], bh[nt >> 1][(nt & 1) * 2],
                                 bh[nt >> 1][(nt & 1) * 2 + 1]);
            }
            __syncthreads();
            chunk++;
        }

        // ---------------- Epilogue (next tile's kt0 load is in flight) -------
        const float l2T = c_l2T;
        float rs0[2] = {0.0f, 0.0f}, rs1[2] = {0.0f, 0.0f};
        float cs[16];
        #pragma unroll
        for (int i = 0; i < 16; i++) cs[i] = 0.0f;

        #pragma unroll
        for (int mt = 0; mt < 2; mt++)
            #pragma unroll
            for (int nt = 0; nt < 8; nt++) {
                const float e0 = ex2(acc[mt][nt][0] * l2T);
                const float e1 = ex2(acc[mt][nt][1] * l2T);
                const float e2 = ex2(acc[mt][nt][2] * l2T);
                const float e3 = ex2(acc[mt][nt][3] * l2T);
                rs0[mt] += e0 + e1;
                rs1[mt] += e2 + e3;
                cs[nt * 2 + 0] += e0 + e2;
                cs[nt * 2 + 1] += e1 + e3;
            }

        #pragma unroll
        for (int off = 1; off <= 2; off <<= 1) {
            #pragma unroll
            for (int mt = 0; mt < 2; mt++) {
                rs0[mt] += __shfl_xor_sync(0xffffffffu, rs0[mt], off);
                rs1[mt] += __shfl_xor_sync(0xffffffffu, rs1[mt], off);
            }
        }
        if ((lane & 3) == 0) {
            const int r8 = lane >> 2;
            #pragma unroll
            for (int mt = 0; mt < 2; mt++) {
                rowScratch[warpN * 128 + warpM * 32 + mt * 16 + 0 + r8] = rs0[mt];
                rowScratch[warpN * 128 + warpM * 32 + mt * 16 + 8 + r8] = rs1[mt];
            }
        }
        if (sym) {
            #pragma unroll
            for (int i = 0; i < 16; i++) {
                #pragma unroll
                for (int off = 4; off <= 16; off <<= 1)
                    cs[i] += __shfl_xor_sync(0xffffffffu, cs[i], off);
            }
            if (lane < 4) {
                #pragma unroll
                for (int nt = 0; nt < 8; nt++) {
                    colScratch[(warpN * 4 + warpM) * 64 + nt * 8 + lane * 2 + 0] = cs[nt * 2 + 0];
                    colScratch[(warpN * 4 + warpM) * 64 + nt * 8 + lane * 2 + 1] = cs[nt * 2 + 1];
                }
            }
        }
        __syncthreads();

        if (tid < 128) {
            const float p = rowScratch[tid] + rowScratch[128 + tid];
            g_partial[(size_t)(rowBase + tid) * NCOLTILES + colTile] = p;
            if (sym) {
                const int wn = tid >> 6, ix = tid & 63;
                float c = colScratch[(wn * 4 + 0) * 64 + ix] + colScratch[(wn * 4 + 1) * 64 + ix]
                        + colScratch[(wn * 4 + 2) * 64 + ix] + colScratch[(wn * 4 + 3) * 64 + ix];
                g_partial[(size_t)(colBase + tid) * NCOLTILES + bx] = c;
            }
        }
        __syncthreads();   // scratch reuse safety for next tile

        if (!hasNext) break;
        tile = nTile; bx = nbx; colTile = nct; sym = nsym;
        rowBase = nRowBase; colBase = nColBase;
    }
}

// ---------------------------------------------------------------------------
// Kernel 3: per-row loss + grid-wide mean (last-block pattern, deterministic).
// ---------------------------------------------------------------------------
__global__ void __launch_bounds__(256) loss_reduce_kernel(float* __restrict__ out) {
    __shared__ float warpLoss[8];
    __shared__ int   isLast;
    const int bid  = blockIdx.x;
    const int row  = bid * 8 + (threadIdx.x >> 5);
    const int lane = threadIdx.x & 31;

    float total = g_partial[(size_t)row * NCOLTILES + lane]
                + g_partial[(size_t)row * NCOLTILES + lane + 32];

    const uint4 va = reinterpret_cast<const uint4*>(g_hi + (size_t)row * D)[lane];
    const uint4 vb = reinterpret_cast<const uint4*>(g_hi + (size_t)(N_ROWS + row) * D)[lane];
    const uint4 vc = reinterpret_cast<const uint4*>(g_hi + (size_t)N_ROWS * D)[lane];

    float dp = 0.0f, d0 = 0.0f;
    {
        const __nv_bfloat162* pa = reinterpret_cast<const __nv_bfloat162*>(&va);
        const __nv_bfloat162* pb = reinterpret_cast<const __nv_bfloat162*>(&vb);
        const __nv_bfloat162* pc = reinterpret_cast<const __nv_bfloat162*>(&vc);
        #pragma unroll
        for (int i = 0; i < 4; i++) {
            float2 fa = __bfloat1622float2(pa[i]);
            float2 fb = __bfloat1622float2(pb[i]);
            float2 fc = __bfloat1622float2(pc[i]);
            dp += fa.x * fb.x + fa.y * fb.y;
            d0 += fa.x * fc.x + fa.y * fc.y;
        }
    }
    #pragma unroll
    for (int off = 16; off > 0; off >>= 1) {
        total += __shfl_xor_sync(0xffffffffu, total, off);
        dp    += __shfl_xor_sync(0xffffffffu, dp, off);
        d0    += __shfl_xor_sync(0xffffffffu, d0, off);
    }
    if (lane == 0) {
        float sum_negs = total - ex2(d0 * c_l2T);
        warpLoss[threadIdx.x >> 5] = logf(sum_negs) - dp * c_invT;
    }
    __syncthreads();

    if (threadIdx.x == 0) {
        float bs = 0.0f;
        #pragma unroll
        for (int i = 0; i < 8; i++) bs += warpLoss[i];
        g_blocksum[bid] = bs;
        __threadfence();
        int old = atomicAdd(&g_counter, 1);
        isLast = (old == NLOSSBLK - 1);
    }
    __syncthreads();

    if (isLast) {
        __shared__ float s[256];
        float v = 0.0f;
        #pragma unroll
        for (int h = 0; h < 2; h++) {
            float t;
            asm volatile("ld.global.cg.f32 %0, [%1];" : "=f"(t)
                         : "l"(g_blocksum + threadIdx.x + h * 256));
            v += t;
        }
        s[threadIdx.x] = v;
        __syncthreads();
        #pragma unroll
        for (int stride = 128; stride > 0; stride >>= 1) {
            if (threadIdx.x < stride) s[threadIdx.x] += s[threadIdx.x + stride];
            __syncthreads();
        }
        if (threadIdx.x == 0) {
            out[0] = s[0] * (1.0f / N_ROWS);
            g_counter = 0;   // reset for graph replay
            g_tileCtr = 0;   // reset work-steal counter for graph replay
        }
    }
}

// ---------------------------------------------------------------------------
extern "C" void kernel_launch(void* const* d_in, const int* in_sizes, int n_in,
                              void* d_out, int out_size) {
    const float* z1 = (const float*)d_in[0];
    const float* z2 = (const float*)d_in[1];
    float* out = (float*)d_out;

    cudaFuncSetAttribute(simsum_mma_kernel,
                         cudaFuncAttributeMaxDynamicSharedMemorySize, SMEM_TOTAL);

    normalize_kernel<<<TWO_N / 8, 256>>>(z1, z2);
    simsum_mma_kernel<<<GRID_GEMM, 256, SMEM_TOTAL>>>();
    loss_reduce_kernel<<<NLOSSBLK, 256>>>(out);
}

// round 10
// speedup vs baseline: 1.3333x; 1.3333x over previous
#include <cuda_runtime.h>
#include <cuda_bf16.h>
#include <math.h>
#include <stdint.h>

#define N_ROWS 4096
#define D      256
#define TWO_N  8192
#define BM 128
#define BN 128
#define BK 32
#define NKT (D / BK)              // 8 k-chunks
#define NCOLTILES 64
#define NLOSSBLK (N_ROWS / 8)     // 512 loss blocks
#define NTILES 1552
#define GRID_GEMM 296             // 2 CTAs per SM, persistent

// exp(x/T) = 2^(x * invT * log2(e))
__device__ __constant__ float c_l2T  = 20.609929f;
__device__ __constant__ float c_invT = 14.285714285714286f;

// Scratch (device globals; no allocation anywhere)
__device__ __nv_bfloat16  g_hi[TWO_N * D];       // bf16 normalized
__device__ float          g_partial[N_ROWS * NCOLTILES];
__device__ float          g_blocksum[NLOSSBLK];
__device__ int            g_counter = 0;         // loss last-block counter

// ---------------------------------------------------------------------------
// PTX helpers (sm_80+ baseline only)
// ---------------------------------------------------------------------------
__device__ __forceinline__ uint32_t smem_to_u32(const void* p) {
    uint32_t a;
    asm("{ .reg .u64 t; cvta.to.shared.u64 t, %1; cvt.u32.u64 %0, t; }" : "=r"(a) : "l"(p));
    return a;
}
__device__ __forceinline__ float ex2(float x) {
    float r;
    asm("ex2.approx.ftz.f32 %0, %1;" : "=f"(r) : "f"(x));
    return r;
}
#define CP_ASYNC16(dst, src) \
    asm volatile("cp.async.cg.shared.global [%0], [%1], 16;" :: "r"(dst), "l"(src))
#define CP_COMMIT() asm volatile("cp.async.commit_group;" ::: "memory")
#define CP_WAIT(n)  asm volatile("cp.async.wait_group %0;" :: "n"(n) : "memory")

__device__ __forceinline__ void ldsm4(uint32_t* r, uint32_t addr) {
    asm volatile("ldmatrix.sync.aligned.m8n8.x4.shared.b16 {%0,%1,%2,%3}, [%4];"
        : "=r"(r[0]), "=r"(r[1]), "=r"(r[2]), "=r"(r[3]) : "r"(addr));
}
__device__ __forceinline__ void mma16816(float* c, const uint32_t* a,
                                         uint32_t b0, uint32_t b1) {
    asm volatile("mma.sync.aligned.m16n8k16.row.col.f32.bf16.bf16.f32 "
        "{%0,%1,%2,%3}, {%4,%5,%6,%7}, {%8,%9}, {%0,%1,%2,%3};"
        : "+f"(c[0]), "+f"(c[1]), "+f"(c[2]), "+f"(c[3])
        : "r"(a[0]), "r"(a[1]), "r"(a[2]), "r"(a[3]), "r"(b0), "r"(b1));
}

// Stage: 128 rows x 128B (8x16B chunks). Chunks 0-3 = A, 4-7 = B.
// XOR swizzle: slot = ch ^ (row & 7) -> conflict-free ldmatrix.
__device__ __forceinline__ uint32_t swadr(uint32_t base, int rowByte, int rm, int ch) {
    return base + rowByte + ((ch ^ rm) << 4);
}

#define STAGE_BYTES 16384
#define NSTAGES     3
#define SCRATCH_OFF (NSTAGES * STAGE_BYTES)      // 49152: epilogue scratch
#define SMEM_TOTAL  (SCRATCH_OFF + 3072)         // 52224 B (2 CTAs/SM fits)

// ---------------------------------------------------------------------------
// Kernel 1: L2-normalize rows -> g_hi (bf16). One warp per row.
// ---------------------------------------------------------------------------
__global__ void __launch_bounds__(256) normalize_kernel(const float* __restrict__ z1,
                                                        const float* __restrict__ z2) {
    const int row  = blockIdx.x * 8 + (threadIdx.x >> 5);
    const int lane = threadIdx.x & 31;
    const float* src = (row < N_ROWS) ? (z1 + (size_t)row * D)
                                      : (z2 + (size_t)(row - N_ROWS) * D);
    float4 a = reinterpret_cast<const float4*>(src)[lane];
    float4 b = reinterpret_cast<const float4*>(src)[lane + 32];
    float ss = a.x*a.x + a.y*a.y + a.z*a.z + a.w*a.w
             + b.x*b.x + b.y*b.y + b.z*b.z + b.w*b.w;
    #pragma unroll
    for (int off = 16; off > 0; off >>= 1)
        ss += __shfl_xor_sync(0xffffffffu, ss, off);
    float scale = 1.0f / fmaxf(sqrtf(ss), 1e-12f);

    float v[8] = {a.x*scale, a.y*scale, a.z*scale, a.w*scale,
                  b.x*scale, b.y*scale, b.z*scale, b.w*scale};
    __nv_bfloat162* dh = reinterpret_cast<__nv_bfloat162*>(g_hi + (size_t)row * D);
    dh[lane * 2 + 0]        = __halves2bfloat162(__float2bfloat16(v[0]), __float2bfloat16(v[1]));
    dh[lane * 2 + 1]        = __halves2bfloat162(__float2bfloat16(v[2]), __float2bfloat16(v[3]));
    dh[(lane + 32) * 2 + 0] = __halves2bfloat162(__float2bfloat16(v[4]), __float2bfloat16(v[5]));
    dh[(lane + 32) * 2 + 1] = __halves2bfloat162(__float2bfloat16(v[6]), __float2bfloat16(v[7]));
}

// ---------------------------------------------------------------------------
// Stage loader: A 128x32 (chunks 0-3) + B 128x32 (chunks 4-7) = 1024 16B chunks
// ---------------------------------------------------------------------------
__device__ __forceinline__ void load_stage(uint32_t stageAddr, int kt,
                                           int rowBase, int colBase, int tid) {
    const int kOff = kt * BK;
    #pragma unroll
    for (int i = 0; i < 4; i++) {
        const int v = i * 256 + tid;
        const int row = v >> 3, ch = v & 7;       // ch 0-3: A, 4-7: B
        const int gRow = (ch < 4) ? (rowBase + row) : (colBase + row);
        const void* src = g_hi + (size_t)gRow * D + kOff + (ch & 3) * 8;
        const uint32_t dst = stageAddr + row * 128 + ((ch ^ (row & 7)) << 4);
        CP_ASYNC16(dst, src);
    }
}

// Tile decode: b<1024 -> right half (bx=b>>5, ct=32+(b&31)); else triangular.
__device__ __forceinline__ void decode_tile(int b, int& bx, int& ct, bool& sym) {
    if (b < 1024) {
        bx = b >> 5; ct = 32 + (b & 31); sym = false;
    } else {
        const int t = b - 1024;
        int e = (int)((sqrtf(8.0f * t + 1.0f) - 1.0f) * 0.5f);
        while ((e + 1) * (e + 2) / 2 <= t) e++;
        while (e * (e + 1) / 2 > t) e--;
        bx = e; ct = t - e * (e + 1) / 2; sym = (ct != bx);
    }
}

// ---------------------------------------------------------------------------
// Kernel 2: persistent HMMA fused sim-GEMM + exp + row/col sums.
// Static tile schedule (tile = blockIdx.x + k*296; decode strictly OUTSIDE
// the kt-loop). 3-stage cp.async ring, ONE __syncthreads per BK=32 chunk:
// the sync both publishes chunk c's data and frees stage (c+2)%3 (computed
// at chunk c-1). Next tile's chunks 0,1 prefetched at kt=6,7.
// ---------------------------------------------------------------------------
__global__ void __launch_bounds__(256, 2) simsum_mma_kernel() {
    extern __shared__ char smem[];
    const uint32_t smem_u32 = smem_to_u32(smem);
    const int tid = threadIdx.x;

    const int lane  = tid & 31;
    const int w     = tid >> 5;
    const int warpM = w >> 1;
    const int warpN = w & 1;

    const int aRow  = warpM * 32 + (lane & 7) + ((lane >> 3) & 1) * 8;
    const int aCh   = (lane >> 4) & 1;
    const int aRm   = aRow & 7;
    const int bRow  = warpN * 64 + (lane & 7) + ((lane >> 4) & 1) * 8;
    const int bCh   = (lane >> 3) & 1;
    const int bRm   = bRow & 7;
    const int aRowByte[2] = {aRow * 128, (aRow + 16) * 128};
    const int bRowByte[4] = {bRow * 128, (bRow + 16) * 128,
                             (bRow + 32) * 128, (bRow + 48) * 128};

    float* rowScratch = reinterpret_cast<float*>(smem + SCRATCH_OFF);        // [2][128]
    float* colScratch = reinterpret_cast<float*>(smem + SCRATCH_OFF) + 256;  // [2][4][64]

    int tile = blockIdx.x;
    int bx, colTile; bool sym;
    decode_tile(tile, bx, colTile, sym);
    int rowBase = bx * BM, colBase = colTile * BN;

    int stageIdx = 0;              // stage of the chunk being computed
    load_stage(smem_u32 + 0 * STAGE_BYTES, 0, rowBase, colBase, tid); CP_COMMIT();
    load_stage(smem_u32 + 1 * STAGE_BYTES, 1, rowBase, colBase, tid); CP_COMMIT();

    #pragma unroll 1
    while (true) {
        // Decode next tile OUTSIDE the kt-loop (register pressure discipline)
        const int nxtTile = tile + GRID_GEMM;
        const bool hasNext = (nxtTile < NTILES);
        int nbx = 0, nct = 0; bool nsym = false;
        if (hasNext) decode_tile(nxtTile, nbx, nct, nsym);
        const int nRowBase = nbx * BM, nColBase = nct * BN;

        float acc[2][8][4];
        #pragma unroll
        for (int mt = 0; mt < 2; mt++)
            #pragma unroll
            for (int nt = 0; nt < 8; nt++)
                #pragma unroll
                for (int r = 0; r < 4; r++) acc[mt][nt][r] = 0.0f;

        #pragma unroll 1
        for (int kt = 0; kt < NKT; kt++) {
            const uint32_t stage = smem_u32 + (uint32_t)stageIdx * STAGE_BYTES;
            int fsIdx = stageIdx + 2; if (fsIdx >= NSTAGES) fsIdx -= NSTAGES;
            const uint32_t fstage = smem_u32 + (uint32_t)fsIdx * STAGE_BYTES;

            if (kt == NKT - 1 && !hasNext) { CP_WAIT(0); } else { CP_WAIT(1); }
            __syncthreads();

            // Issue load of chunk+2 into the freed stage
            if (kt + 2 < NKT) {
                load_stage(fstage, kt + 2, rowBase, colBase, tid); CP_COMMIT();
            } else if (hasNext) {
                load_stage(fstage, kt + 2 - NKT, nRowBase, nColBase, tid); CP_COMMIT();
            }

            #pragma unroll
            for (int s = 0; s < 2; s++) {
                uint32_t ah[2][4], bh[4][4];
                #pragma unroll
                for (int mt = 0; mt < 2; mt++)
                    ldsm4(ah[mt], swadr(stage, aRowByte[mt], aRm, 2 * s + aCh));
                #pragma unroll
                for (int p = 0; p < 4; p++)
                    ldsm4(bh[p], swadr(stage, bRowByte[p], bRm, 4 + 2 * s + bCh));
                #pragma unroll
                for (int mt = 0; mt < 2; mt++)
                    #pragma unroll
                    for (int nt = 0; nt < 8; nt++)
                        mma16816(acc[mt][nt], ah[mt], bh[nt >> 1][(nt & 1) * 2],
                                 bh[nt >> 1][(nt & 1) * 2 + 1]);
            }
            stageIdx++; if (stageIdx >= NSTAGES) stageIdx -= NSTAGES;
        }

        // ---------------- Epilogue (next tile's chunks 0,1 in flight) --------
        const float l2T = c_l2T;
        float rs0[2] = {0.0f, 0.0f}, rs1[2] = {0.0f, 0.0f};
        float cs[16];
        #pragma unroll
        for (int i = 0; i < 16; i++) cs[i] = 0.0f;

        #pragma unroll
        for (int mt = 0; mt < 2; mt++)
            #pragma unroll
            for (int nt = 0; nt < 8; nt++) {
                const float e0 = ex2(acc[mt][nt][0] * l2T);
                const float e1 = ex2(acc[mt][nt][1] * l2T);
                const float e2 = ex2(acc[mt][nt][2] * l2T);
                const float e3 = ex2(acc[mt][nt][3] * l2T);
                rs0[mt] += e0 + e1;
                rs1[mt] += e2 + e3;
                cs[nt * 2 + 0] += e0 + e2;
                cs[nt * 2 + 1] += e1 + e3;
            }

        #pragma unroll
        for (int off = 1; off <= 2; off <<= 1) {
            #pragma unroll
            for (int mt = 0; mt < 2; mt++) {
                rs0[mt] += __shfl_xor_sync(0xffffffffu, rs0[mt], off);
                rs1[mt] += __shfl_xor_sync(0xffffffffu, rs1[mt], off);
            }
        }
        if ((lane & 3) == 0) {
            const int r8 = lane >> 2;
            #pragma unroll
            for (int mt = 0; mt < 2; mt++) {
                rowScratch[warpN * 128 + warpM * 32 + mt * 16 + 0 + r8] = rs0[mt];
                rowScratch[warpN * 128 + warpM * 32 + mt * 16 + 8 + r8] = rs1[mt];
            }
        }
        if (sym) {
            #pragma unroll
            for (int i = 0; i < 16; i++) {
                #pragma unroll
                for (int off = 4; off <= 16; off <<= 1)
                    cs[i] += __shfl_xor_sync(0xffffffffu, cs[i], off);
            }
            if (lane < 4) {
                #pragma unroll
                for (int nt = 0; nt < 8; nt++) {
                    colScratch[(warpN * 4 + warpM) * 64 + nt * 8 + lane * 2 + 0] = cs[nt * 2 + 0];
                    colScratch[(warpN * 4 + warpM) * 64 + nt * 8 + lane * 2 + 1] = cs[nt * 2 + 1];
                }
            }
        }
        __syncthreads();

        if (tid < 128) {
            const float p = rowScratch[tid] + rowScratch[128 + tid];
            g_partial[(size_t)(rowBase + tid) * NCOLTILES + colTile] = p;
            if (sym) {
                const int wn = tid >> 6, ix = tid & 63;
                float c = colScratch[(wn * 4 + 0) * 64 + ix] + colScratch[(wn * 4 + 1) * 64 + ix]
                        + colScratch[(wn * 4 + 2) * 64 + ix] + colScratch[(wn * 4 + 3) * 64 + ix];
                g_partial[(size_t)(colBase + tid) * NCOLTILES + bx] = c;
            }
        }
        __syncthreads();   // scratch reuse safety for next tile

        if (!hasNext) break;
        tile = nxtTile; bx = nbx; colTile = nct; sym = nsym;
        rowBase = nRowBase; colBase = nColBase;
    }
}

// ---------------------------------------------------------------------------
// Kernel 3: per-row loss + grid-wide mean (last-block pattern, deterministic).
// ---------------------------------------------------------------------------
__global__ void __launch_bounds__(256) loss_reduce_kernel(float* __restrict__ out) {
    __shared__ float warpLoss[8];
    __shared__ int   isLast;
    const int bid  = blockIdx.x;
    const int row  = bid * 8 + (threadIdx.x >> 5);
    const int lane = threadIdx.x & 31;

    float total = g_partial[(size_t)row * NCOLTILES + lane]
                + g_partial[(size_t)row * NCOLTILES + lane + 32];

    const uint4 va = reinterpret_cast<const uint4*>(g_hi + (size_t)row * D)[lane];
    const uint4 vb = reinterpret_cast<const uint4*>(g_hi + (size_t)(N_ROWS + row) * D)[lane];
    const uint4 vc = reinterpret_cast<const uint4*>(g_hi + (size_t)N_ROWS * D)[lane];

    float dp = 0.0f, d0 = 0.0f;
    {
        const __nv_bfloat162* pa = reinterpret_cast<const __nv_bfloat162*>(&va);
        const __nv_bfloat162* pb = reinterpret_cast<const __nv_bfloat162*>(&vb);
        const __nv_bfloat162* pc = reinterpret_cast<const __nv_bfloat162*>(&vc);
        #pragma unroll
        for (int i = 0; i < 4; i++) {
            float2 fa = __bfloat1622float2(pa[i]);
            float2 fb = __bfloat1622float2(pb[i]);
            float2 fc = __bfloat1622float2(pc[i]);
            dp += fa.x * fb.x + fa.y * fb.y;
            d0 += fa.x * fc.x + fa.y * fc.y;
        }
    }
    #pragma unroll
    for (int off = 16; off > 0; off >>= 1) {
        total += __shfl_xor_sync(0xffffffffu, total, off);
        dp    += __shfl_xor_sync(0xffffffffu, dp, off);
        d0    += __shfl_xor_sync(0xffffffffu, d0, off);
    }
    if (lane == 0) {
        float sum_negs = total - ex2(d0 * c_l2T);
        warpLoss[threadIdx.x >> 5] = logf(sum_negs) - dp * c_invT;
    }
    __syncthreads();

    if (threadIdx.x == 0) {
        float bs = 0.0f;
        #pragma unroll
        for (int i = 0; i < 8; i++) bs += warpLoss[i];
        g_blocksum[bid] = bs;
        __threadfence();
        int old = atomicAdd(&g_counter, 1);
        isLast = (old == NLOSSBLK - 1);
    }
    __syncthreads();

    if (isLast) {
        __shared__ float s[256];
        float v = 0.0f;
        #pragma unroll
        for (int h = 0; h < 2; h++) {
            float t;
            asm volatile("ld.global.cg.f32 %0, [%1];" : "=f"(t)
                         : "l"(g_blocksum + threadIdx.x + h * 256));
            v += t;
        }
        s[threadIdx.x] = v;
        __syncthreads();
        #pragma unroll
        for (int stride = 128; stride > 0; stride >>= 1) {
            if (threadIdx.x < stride) s[threadIdx.x] += s[threadIdx.x + stride];
            __syncthreads();
        }
        if (threadIdx.x == 0) {
            out[0] = s[0] * (1.0f / N_ROWS);
            g_counter = 0;   // reset for graph replay
        }
    }
}

// ---------------------------------------------------------------------------
extern "C" void kernel_launch(void* const* d_in, const int* in_sizes, int n_in,
                              void* d_out, int out_size) {
    const float* z1 = (const float*)d_in[0];
    const float* z2 = (const float*)d_in[1];
    float* out = (float*)d_out;

    cudaFuncSetAttribute(simsum_mma_kernel,
                         cudaFuncAttributeMaxDynamicSharedMemorySize, SMEM_TOTAL);

    normalize_kernel<<<TWO_N / 8, 256>>>(z1, z2);
    simsum_mma_kernel<<<GRID_GEMM, 256, SMEM_TOTAL>>>();
    loss_reduce_kernel<<<NLOSSBLK, 256>>>(out);
}